// round 7
// baseline (speedup 1.0000x reference)
#include <cuda_runtime.h>
#include <math.h>

#define Nn 100000
#define Ee 1600000
#define ETOT (Ee + Nn)
#define Hh 64
#define Gg 512
#define CAP 160   // smem-cached logits per dst; deg>CAP uses recompute fallback

// ---------------- device scratch (no allocation allowed) ----------------
__device__ __align__(256) float g_h[(size_t)Nn * Hh];    // h = xW
__device__ __align__(256) float g_agg[(size_t)Nn * Hh];  // normalized attention output
__device__ float g_ls[Nn];
__device__ float g_ld[Nn];
__device__ float g_pool[Gg * Hh];
__device__ int   g_deg[Nn];
__device__ int   g_rowptr[Nn + 1];
__device__ int   g_cursor[Nn];
__device__ int   g_csrc[ETOT];
__device__ int   g_src[ETOT];
__device__ int   g_dst[ETOT];
__device__ int   g_batch[Nn];
__device__ int   g_ei32, g_b32;   // dtype flags: 1 = buffer is int32, 0 = int64

// ================= dtype probe (decides on-device; capture-safe) ============
__global__ void probe_kernel(const void* ei, const void* batch) {
    int tid = threadIdx.x;           // 256 threads, 1 block
    if (tid == 0) { g_ei32 = 0; g_b32 = 0; }
    __syncthreads();
    // edge probe: safe range under both interps is [0, Ee) int64 slots
    const long long* e64 = (const long long*)ei;
    long long v = e64[(tid * 997) % Ee];
    if ((unsigned long long)v >= (unsigned long long)Nn) atomicOr(&g_ei32, 1);
    // batch probe: safe range is [0, Nn/2) int64 slots; stride across it
    const long long* b64 = (const long long*)batch;
    long long w = b64[(long long)tid * (Nn / 2 - 1) / 255];
    if ((unsigned long long)w >= (unsigned long long)Gg) atomicOr(&g_b32, 1);
}

__global__ void convert_edges_kernel(const void* ei) {
    int i = blockIdx.x * 256 + threadIdx.x;
    if (i >= ETOT) return;
    int src, dst;
    if (i < Ee) {
        if (g_ei32) {
            const int* p = (const int*)ei;
            src = p[i]; dst = p[Ee + i];
        } else {
            const long long* p = (const long long*)ei;
            src = (int)p[i]; dst = (int)p[Ee + i];
        }
    } else {
        src = dst = i - Ee;   // self loops
    }
    g_src[i] = src;
    g_dst[i] = dst;
}

__global__ void convert_batch_kernel(const void* b) {
    int i = blockIdx.x * 256 + threadIdx.x;
    if (i >= Nn) return;
    g_batch[i] = g_b32 ? ((const int*)b)[i] : (int)((const long long*)b)[i];
}

// ================= CSR build (int atomics only) =================
__global__ void zero_deg_kernel() {
    int i = blockIdx.x * 256 + threadIdx.x;
    if (i < Nn) g_deg[i] = 0;
}

__global__ void count_kernel() {
    int i = blockIdx.x * 256 + threadIdx.x;
    if (i >= ETOT) return;
    atomicAdd(&g_deg[g_dst[i]], 1);
}

// single-block exclusive scan over g_deg -> g_rowptr, g_cursor
__global__ void scan_kernel() {
    __shared__ int warp_sums[32];
    __shared__ int s_carry;
    int tid = threadIdx.x;            // 1024 threads
    int lane = tid & 31, wid = tid >> 5;
    if (tid == 0) s_carry = 0;
    __syncthreads();
    for (int base = 0; base < Nn; base += 1024) {
        int i = base + tid;
        int v = (i < Nn) ? g_deg[i] : 0;
        int x = v;
#pragma unroll
        for (int off = 1; off < 32; off <<= 1) {
            int y = __shfl_up_sync(0xffffffffu, x, off);
            if (lane >= off) x += y;
        }
        if (lane == 31) warp_sums[wid] = x;
        __syncthreads();
        if (wid == 0) {
            int w = warp_sums[lane];
#pragma unroll
            for (int off = 1; off < 32; off <<= 1) {
                int y = __shfl_up_sync(0xffffffffu, w, off);
                if (lane >= off) w += y;
            }
            warp_sums[lane] = w;
        }
        __syncthreads();
        int warp_off = (wid == 0) ? 0 : warp_sums[wid - 1];
        int excl = s_carry + warp_off + x - v;
        if (i < Nn) { g_rowptr[i] = excl; g_cursor[i] = excl; }
        __syncthreads();
        if (tid == 0) s_carry += warp_sums[31];
        __syncthreads();
    }
    if (tid == 0) g_rowptr[Nn] = ETOT;
}

__global__ void scatter_kernel() {
    int i = blockIdx.x * 256 + threadIdx.x;
    if (i >= ETOT) return;
    int pos = atomicAdd(&g_cursor[g_dst[i]], 1);
    g_csrc[pos] = g_src[i];
}

// ================= GEMM: h = X @ W, ls = h.a_s, ld = h.a_d =================
// Block = 256 threads = 4 nodes x 64 outputs. W staged in shared.
// For layers >= 1 the input is elu(g_agg + b_prev)  (g_agg already normalized).
template <int F, bool TRANS>
__global__ void gemm_kernel(const float* __restrict__ xin,
                            const float* __restrict__ W,
                            const float* __restrict__ a_s,
                            const float* __restrict__ a_d,
                            const float* __restrict__ bprev) {
    __shared__ float Ws[F * Hh];
    __shared__ float xs[4][F];
    __shared__ float as_s[Hh], ad_s[Hh], bs[Hh];
    __shared__ float ssum[8][2];

    int tid = threadIdx.x;
    for (int i = tid; i < F * Hh; i += 256) Ws[i] = W[i];
    if (tid < Hh) {
        as_s[tid] = a_s[tid];
        ad_s[tid] = a_d[tid];
        if (TRANS) bs[tid] = bprev[tid];
    }
    __syncthreads();

    int local = tid >> 6;
    int j     = tid & 63;
    int n     = blockIdx.x * 4 + local;

    if (TRANS) {
        float v = g_agg[(size_t)n * Hh + j] + bs[j];
        xs[local][j] = v > 0.f ? v : (expf(v) - 1.f);   // ELU
    } else {
        if (j < F) xs[local][j] = xin[n * F + j];
    }
    __syncthreads();

    float acc = 0.f;
#pragma unroll
    for (int k = 0; k < F; k++) acc += xs[local][k] * Ws[k * Hh + j];
    g_h[(size_t)n * Hh + j] = acc;

    float rs = acc * as_s[j];
    float rd = acc * ad_s[j];
#pragma unroll
    for (int off = 16; off; off >>= 1) {
        rs += __shfl_down_sync(0xffffffffu, rs, off);
        rd += __shfl_down_sync(0xffffffffu, rd, off);
    }
    int warp = tid >> 5;
    if ((tid & 31) == 0) { ssum[warp][0] = rs; ssum[warp][1] = rd; }
    __syncthreads();
    if (j == 0) {
        g_ls[n] = ssum[2 * local][0] + ssum[2 * local + 1][0];
        g_ld[n] = ssum[2 * local][1] + ssum[2 * local + 1][1];
    }
}

// ============== aggregation: one warp per dst, CSR gather, no atomics =======
__global__ void agg_kernel() {
    __shared__ float se[8][CAP];
    int gwarp = (blockIdx.x * 256 + threadIdx.x) >> 5;
    int lane  = threadIdx.x & 31;
    int wl    = threadIdx.x >> 5;
    if (gwarp >= Nn) return;
    int dst = gwarp;
    int r0 = g_rowptr[dst], r1 = g_rowptr[dst + 1];
    int d  = r1 - r0;
    float ldv = g_ld[dst];

    // pass 1: logits + max (cache into smem up to CAP)
    float m = -INFINITY;
    for (int k = lane; k < d; k += 32) {
        int src = g_csrc[r0 + k];
        float e = g_ls[src] + ldv;
        e = e > 0.f ? e : 0.2f * e;
        if (k < CAP) se[wl][k] = e;
        m = fmaxf(m, e);
    }
#pragma unroll
    for (int off = 16; off; off >>= 1)
        m = fmaxf(m, __shfl_xor_sync(0xffffffffu, m, off));
    __syncwarp();

    // pass 2: weighted accumulation (2 coalesced 128B loads per edge)
    float den = 0.f, a0 = 0.f, a1 = 0.f;
    for (int k = 0; k < d; k++) {
        int src = g_csrc[r0 + k];
        float e;
        if (k < CAP) e = se[wl][k];
        else { e = g_ls[src] + ldv; e = e > 0.f ? e : 0.2f * e; }
        float ex = __expf(e - m);
        den += ex;
        const float* hp = g_h + (size_t)src * Hh;
        a0 += ex * hp[lane];
        a1 += ex * hp[lane + 32];
    }
    float inv = 1.f / den;
    g_agg[(size_t)dst * Hh + lane]      = a0 * inv;
    g_agg[(size_t)dst * Hh + lane + 32] = a1 * inv;
}

// ================= pooling: batch is sorted -> contiguous ranges ============
__device__ __forceinline__ int lower_bound_batch(int key) {
    int lo = 0, hi = Nn;
    while (lo < hi) {
        int mid = (lo + hi) >> 1;
        if (g_batch[mid] < key) lo = mid + 1; else hi = mid;
    }
    return lo;
}

__global__ void pool_kernel(const float* __restrict__ b4) {
    __shared__ int s_lo, s_hi;
    int g = blockIdx.x, j = threadIdx.x;   // 64 threads
    if (j == 0) s_lo = lower_bound_batch(g);
    if (j == 1) s_hi = lower_bound_batch(g + 1);
    __syncthreads();
    float bj = b4[j];
    float mx = -INFINITY;
    for (int n = s_lo; n < s_hi; n++) {
        float v = g_agg[(size_t)n * Hh + j] + bj;
        v = v > 0.f ? v : (expf(v) - 1.f);
        mx = fmaxf(mx, v);
    }
    g_pool[g * Hh + j] = mx;   // -inf for empty graphs -> 0 in final kernel
}

// ================= final linear =================
__global__ void final_kernel(const float* __restrict__ lw,
                             const float* __restrict__ lb,
                             float* __restrict__ out) {
    int g = blockIdx.x, j = threadIdx.x;   // 64 threads
    float p = g_pool[g * Hh + j];
    if (!isfinite(p)) p = 0.f;
    float c0 = p * lw[j * 2 + 0];
    float c1 = p * lw[j * 2 + 1];
#pragma unroll
    for (int off = 16; off; off >>= 1) {
        c0 += __shfl_down_sync(0xffffffffu, c0, off);
        c1 += __shfl_down_sync(0xffffffffu, c1, off);
    }
    __shared__ float s[2][2];
    if ((j & 31) == 0) { s[j >> 5][0] = c0; s[j >> 5][1] = c1; }
    __syncthreads();
    if (j == 0) {
        out[2 * g + 0] = s[0][0] + s[1][0] + lb[0];
        out[2 * g + 1] = s[0][1] + s[1][1] + lb[1];
    }
}

// ================= launch =================
extern "C" void kernel_launch(void* const* d_in, const int* in_sizes, int n_in,
                              void* d_out, int out_size) {
    const float* x     = (const float*)d_in[0];
    const void*  ei    = d_in[1];
    const void*  batch = d_in[2];
    const float *W[5], *as[5], *ad[5], *b[5];
    for (int l = 0; l < 5; l++) {
        W[l]  = (const float*)d_in[3 + 4 * l];
        as[l] = (const float*)d_in[4 + 4 * l];
        ad[l] = (const float*)d_in[5 + 4 * l];
        b[l]  = (const float*)d_in[6 + 4 * l];
    }
    const float* lw = (const float*)d_in[23];
    const float* lb = (const float*)d_in[24];
    float* out = (float*)d_out;

    // dtype-agnostic ingestion + CSR build (edge structure is layer-invariant)
    probe_kernel<<<1, 256>>>(ei, batch);
    convert_edges_kernel<<<(ETOT + 255) / 256, 256>>>(ei);
    convert_batch_kernel<<<(Nn + 255) / 256, 256>>>(batch);
    zero_deg_kernel<<<(Nn + 255) / 256, 256>>>();
    count_kernel<<<(ETOT + 255) / 256, 256>>>();
    scan_kernel<<<1, 1024>>>();
    scatter_kernel<<<(ETOT + 255) / 256, 256>>>();

    for (int l = 0; l < 5; l++) {
        if (l == 0)
            gemm_kernel<14, false><<<Nn / 4, 256>>>(x, W[0], as[0], ad[0], nullptr);
        else
            gemm_kernel<64, true><<<Nn / 4, 256>>>(nullptr, W[l], as[l], ad[l], b[l - 1]);
        agg_kernel<<<(Nn * 32 + 255) / 256, 256>>>();
    }
    pool_kernel<<<Gg, 64>>>(b[4]);
    final_kernel<<<Gg, 64>>>(lw, lb, out);
}

// round 8
// speedup vs baseline: 1.1705x; 1.1705x over previous
#include <cuda_runtime.h>
#include <math.h>

#define Nn 100000
#define Ee 1600000
#define ETOT (Ee + Nn)
#define Hh 64
#define Gg 512
#define CAP 160   // smem-cached logits per dst; deg>CAP uses recompute fallback
#define NB 98     // ceil(Nn/1024) scan blocks

// ---------------- device scratch (no allocation allowed) ----------------
__device__ __align__(256) float g_h[(size_t)Nn * Hh];    // h = xW
__device__ __align__(256) float g_agg[(size_t)Nn * Hh];  // normalized attention output
__device__ float g_ls[Nn];
__device__ float g_ld[Nn];
__device__ float g_pool[Gg * Hh];
__device__ int   g_deg[Nn];
__device__ int   g_rowptr[Nn + 1];
__device__ int   g_cursor[Nn];
__device__ int   g_csrc[ETOT];
__device__ int   g_src[ETOT];
__device__ int   g_dst[ETOT];
__device__ int   g_batch[Nn];
__device__ int   g_bsum[NB], g_boff[NB];
__device__ int   g_ei32, g_b32;   // dtype flags: 1 = int32 packing, 0 = int64

// ============ zero degrees + dtype probe (fused; capture-safe) ============
__global__ void zeroprobe_kernel(const void* ei, const void* batch) {
    if (blockIdx.x < 391) {
        int i = blockIdx.x * 256 + threadIdx.x;
        if (i < Nn) g_deg[i] = 0;
    } else {
        int tid = threadIdx.x;
        if (tid == 0) { g_ei32 = 0; g_b32 = 0; }
        __syncthreads();
        // safe to read [0,Ee) int64 slots under both interpretations
        const long long* e64 = (const long long*)ei;
        long long v = e64[(tid * 997) % Ee];
        if ((unsigned long long)v >= (unsigned long long)Nn) atomicOr(&g_ei32, 1);
        const long long* b64 = (const long long*)batch;
        long long w = b64[(long long)tid * (Nn / 2 - 1) / 255];
        if ((unsigned long long)w >= (unsigned long long)Gg) atomicOr(&g_b32, 1);
    }
}

// ============ convert edges + count degrees (fused) ============
__global__ void convert_count_kernel(const void* ei) {
    int i = blockIdx.x * 256 + threadIdx.x;
    if (i >= ETOT) return;
    int src, dst;
    if (i < Ee) {
        if (g_ei32) {
            const int* p = (const int*)ei;
            src = p[i]; dst = p[Ee + i];
        } else {
            const long long* p = (const long long*)ei;
            src = (int)p[i]; dst = (int)p[Ee + i];
        }
    } else {
        src = dst = i - Ee;   // self loops
    }
    g_src[i] = src;
    g_dst[i] = dst;
    atomicAdd(&g_deg[dst], 1);
}

// ============ 3-phase multi-block exclusive scan ============
__global__ void scanA_kernel() {   // per-block local exclusive scan + totals
    __shared__ int warp_sums[32];
    int tid = threadIdx.x, lane = tid & 31, wid = tid >> 5;
    int i = blockIdx.x * 1024 + tid;
    int v = (i < Nn) ? g_deg[i] : 0;
    int x = v;
#pragma unroll
    for (int off = 1; off < 32; off <<= 1) {
        int y = __shfl_up_sync(0xffffffffu, x, off);
        if (lane >= off) x += y;
    }
    if (lane == 31) warp_sums[wid] = x;
    __syncthreads();
    if (wid == 0) {
        int w = warp_sums[lane];
#pragma unroll
        for (int off = 1; off < 32; off <<= 1) {
            int y = __shfl_up_sync(0xffffffffu, w, off);
            if (lane >= off) w += y;
        }
        warp_sums[lane] = w;
    }
    __syncthreads();
    int woff = wid ? warp_sums[wid - 1] : 0;
    if (i < Nn) g_rowptr[i] = woff + x - v;
    if (tid == 0) g_bsum[blockIdx.x] = warp_sums[31];
}

__global__ void scanB_kernel() {   // scan the NB block totals (128 threads)
    __shared__ int ws[4];
    int tid = threadIdx.x, lane = tid & 31, wid = tid >> 5;
    int v = (tid < NB) ? g_bsum[tid] : 0;
    int x = v;
#pragma unroll
    for (int off = 1; off < 32; off <<= 1) {
        int y = __shfl_up_sync(0xffffffffu, x, off);
        if (lane >= off) x += y;
    }
    if (lane == 31) ws[wid] = x;
    __syncthreads();
    int woff = 0;
    for (int k = 0; k < wid; k++) woff += ws[k];
    if (tid < NB) g_boff[tid] = woff + x - v;
    if (tid == 0) g_rowptr[Nn] = ETOT;
}

__global__ void scanC_kernel(const void* batch) {  // apply offsets + batch cvt
    int i = blockIdx.x * 1024 + threadIdx.x;
    if (i >= Nn) return;
    int r = g_rowptr[i] + g_boff[blockIdx.x];
    g_rowptr[i] = r;
    g_cursor[i] = r;
    g_batch[i] = g_b32 ? ((const int*)batch)[i] : (int)((const long long*)batch)[i];
}

__global__ void scatter_kernel() {
    int i = blockIdx.x * 256 + threadIdx.x;
    if (i >= ETOT) return;
    int pos = atomicAdd(&g_cursor[g_dst[i]], 1);
    g_csrc[pos] = g_src[i];
}

// ================= GEMM: h = X @ W, ls = h.a_s, ld = h.a_d =================
template <int F, bool TRANS>
__global__ void gemm_kernel(const float* __restrict__ xin,
                            const float* __restrict__ W,
                            const float* __restrict__ a_s,
                            const float* __restrict__ a_d,
                            const float* __restrict__ bprev) {
    __shared__ float Ws[F * Hh];
    __shared__ float xs[4][F];
    __shared__ float as_s[Hh], ad_s[Hh], bs[Hh];
    __shared__ float ssum[8][2];

    int tid = threadIdx.x;
    for (int i = tid; i < F * Hh; i += 256) Ws[i] = W[i];
    if (tid < Hh) {
        as_s[tid] = a_s[tid];
        ad_s[tid] = a_d[tid];
        if (TRANS) bs[tid] = bprev[tid];
    }
    __syncthreads();

    int local = tid >> 6;
    int j     = tid & 63;
    int n     = blockIdx.x * 4 + local;

    if (TRANS) {
        float v = g_agg[(size_t)n * Hh + j] + bs[j];
        xs[local][j] = v > 0.f ? v : (expf(v) - 1.f);   // ELU
    } else {
        if (j < F) xs[local][j] = xin[n * F + j];
    }
    __syncthreads();

    float acc = 0.f;
#pragma unroll
    for (int k = 0; k < F; k++) acc += xs[local][k] * Ws[k * Hh + j];
    g_h[(size_t)n * Hh + j] = acc;

    float rs = acc * as_s[j];
    float rd = acc * ad_s[j];
#pragma unroll
    for (int off = 16; off; off >>= 1) {
        rs += __shfl_down_sync(0xffffffffu, rs, off);
        rd += __shfl_down_sync(0xffffffffu, rd, off);
    }
    int warp = tid >> 5;
    if ((tid & 31) == 0) { ssum[warp][0] = rs; ssum[warp][1] = rd; }
    __syncthreads();
    if (j == 0) {
        g_ls[n] = ssum[2 * local][0] + ssum[2 * local + 1][0];
        g_ld[n] = ssum[2 * local][1] + ssum[2 * local + 1][1];
    }
}

// ====== aggregation: warp/dst, CSR gather, 2 edges per iteration ======
__global__ void agg_kernel() {
    __shared__ float se[8][CAP];
    int gwarp = (blockIdx.x * 256 + threadIdx.x) >> 5;
    int lane  = threadIdx.x & 31;
    int wl    = threadIdx.x >> 5;
    if (gwarp >= Nn) return;
    int dst = gwarp;
    int r0 = g_rowptr[dst], r1 = g_rowptr[dst + 1];
    int d  = r1 - r0;
    float ldv = g_ld[dst];

    // pass 1: logits + max (cache into smem up to CAP)
    float m = -INFINITY;
    for (int k = lane; k < d; k += 32) {
        int src = g_csrc[r0 + k];
        float e = g_ls[src] + ldv;
        e = e > 0.f ? e : 0.2f * e;
        if (k < CAP) se[wl][k] = e;
        m = fmaxf(m, e);
    }
#pragma unroll
    for (int off = 16; off; off >>= 1)
        m = fmaxf(m, __shfl_xor_sync(0xffffffffu, m, off));
    __syncwarp();

    // pass 2: half-warp per edge (float4 slice), 2 edges in flight
    int sub = lane >> 4;      // which edge of the pair
    int l16 = lane & 15;      // float4 column slice
    float4 acc = make_float4(0.f, 0.f, 0.f, 0.f);
    float den = 0.f;
    for (int kk = sub; kk < d; kk += 2) {
        int src = g_csrc[r0 + kk];
        float e;
        if (kk < CAP) e = se[wl][kk];
        else { e = g_ls[src] + ldv; e = e > 0.f ? e : 0.2f * e; }
        float ex = __expf(e - m);
        den += ex;
        const float4 hv = *reinterpret_cast<const float4*>(g_h + (size_t)src * Hh + l16 * 4);
        acc.x += ex * hv.x; acc.y += ex * hv.y;
        acc.z += ex * hv.z; acc.w += ex * hv.w;
    }
    // combine the two halves
    den   += __shfl_xor_sync(0xffffffffu, den,   16);
    acc.x += __shfl_xor_sync(0xffffffffu, acc.x, 16);
    acc.y += __shfl_xor_sync(0xffffffffu, acc.y, 16);
    acc.z += __shfl_xor_sync(0xffffffffu, acc.z, 16);
    acc.w += __shfl_xor_sync(0xffffffffu, acc.w, 16);
    if (sub == 0) {
        float inv = 1.f / den;
        float4 o = make_float4(acc.x * inv, acc.y * inv, acc.z * inv, acc.w * inv);
        *reinterpret_cast<float4*>(g_agg + (size_t)dst * Hh + l16 * 4) = o;
    }
}

// ================= pooling: sorted batch -> contiguous ranges ============
__device__ __forceinline__ int lower_bound_batch(int key) {
    int lo = 0, hi = Nn;
    while (lo < hi) {
        int mid = (lo + hi) >> 1;
        if (g_batch[mid] < key) lo = mid + 1; else hi = mid;
    }
    return lo;
}

__global__ void pool_kernel(const float* __restrict__ b4) {
    __shared__ int s_lo, s_hi;
    __shared__ float red[4][Hh];
    int g = blockIdx.x;
    int tid = threadIdx.x;          // 256 threads
    int j = tid & 63, c = tid >> 6;
    if (tid == 0) s_lo = lower_bound_batch(g);
    if (tid == 1) s_hi = lower_bound_batch(g + 1);
    __syncthreads();
    float bj = b4[j];
    float mx = -INFINITY;
    for (int n = s_lo + c; n < s_hi; n += 4) {
        float v = g_agg[(size_t)n * Hh + j] + bj;
        v = v > 0.f ? v : (expf(v) - 1.f);
        mx = fmaxf(mx, v);
    }
    red[c][j] = mx;
    __syncthreads();
    if (c == 0) {
        mx = fmaxf(fmaxf(red[0][j], red[1][j]), fmaxf(red[2][j], red[3][j]));
        g_pool[g * Hh + j] = mx;   // -inf for empty graphs -> 0 in final kernel
    }
}

// ================= final linear =================
__global__ void final_kernel(const float* __restrict__ lw,
                             const float* __restrict__ lb,
                             float* __restrict__ out) {
    int g = blockIdx.x, j = threadIdx.x;   // 64 threads
    float p = g_pool[g * Hh + j];
    if (!isfinite(p)) p = 0.f;
    float c0 = p * lw[j * 2 + 0];
    float c1 = p * lw[j * 2 + 1];
#pragma unroll
    for (int off = 16; off; off >>= 1) {
        c0 += __shfl_down_sync(0xffffffffu, c0, off);
        c1 += __shfl_down_sync(0xffffffffu, c1, off);
    }
    __shared__ float s[2][2];
    if ((j & 31) == 0) { s[j >> 5][0] = c0; s[j >> 5][1] = c1; }
    __syncthreads();
    if (j == 0) {
        out[2 * g + 0] = s[0][0] + s[1][0] + lb[0];
        out[2 * g + 1] = s[0][1] + s[1][1] + lb[1];
    }
}

// ================= launch =================
extern "C" void kernel_launch(void* const* d_in, const int* in_sizes, int n_in,
                              void* d_out, int out_size) {
    const float* x     = (const float*)d_in[0];
    const void*  ei    = d_in[1];
    const void*  batch = d_in[2];
    const float *W[5], *as[5], *ad[5], *b[5];
    for (int l = 0; l < 5; l++) {
        W[l]  = (const float*)d_in[3 + 4 * l];
        as[l] = (const float*)d_in[4 + 4 * l];
        ad[l] = (const float*)d_in[5 + 4 * l];
        b[l]  = (const float*)d_in[6 + 4 * l];
    }
    const float* lw = (const float*)d_in[23];
    const float* lb = (const float*)d_in[24];
    float* out = (float*)d_out;

    // ingestion + CSR build (edge structure is layer-invariant)
    zeroprobe_kernel<<<392, 256>>>(ei, batch);
    convert_count_kernel<<<(ETOT + 255) / 256, 256>>>(ei);
    scanA_kernel<<<NB, 1024>>>();
    scanB_kernel<<<1, 128>>>();
    scanC_kernel<<<NB, 1024>>>(batch);
    scatter_kernel<<<(ETOT + 255) / 256, 256>>>();

    for (int l = 0; l < 5; l++) {
        if (l == 0)
            gemm_kernel<14, false><<<Nn / 4, 256>>>(x, W[0], as[0], ad[0], nullptr);
        else
            gemm_kernel<64, true><<<Nn / 4, 256>>>(nullptr, W[l], as[l], ad[l], b[l - 1]);
        agg_kernel<<<(Nn * 32 + 255) / 256, 256>>>();
    }
    pool_kernel<<<Gg, 256>>>(b[4]);
    final_kernel<<<Gg, 64>>>(lw, lb, out);
}

// round 10
// speedup vs baseline: 1.7354x; 1.4827x over previous
#include <cuda_runtime.h>
#include <cuda_fp16.h>
#include <math.h>

#define Nn 100000
#define Ee 1600000
#define ETOT (Ee + Nn)
#define Hh 64
#define Gg 512
#define CAP 160   // smem-cached logits per dst; deg>CAP uses recompute fallback
#define NB 98     // ceil(Nn/1024) scan blocks

// ---------------- device scratch (no allocation allowed) ----------------
__device__ __align__(256) __half g_hh[(size_t)Nn * Hh];  // h = xW (fp16)
__device__ __align__(256) float g_agg[(size_t)Nn * Hh];  // normalized attention output
__device__ float g_ls[Nn];
__device__ float g_ld[Nn];
__device__ float g_pool[Gg * Hh];
__device__ int   g_deg[Nn];
__device__ int   g_rowptr[Nn + 1];
__device__ int   g_cursor[Nn];
__device__ int   g_csrc[ETOT];
__device__ int   g_batch[Nn];
__device__ int   g_bsum[NB], g_boff[NB];
__device__ int   g_ei32, g_b32;   // dtype flags: 1 = int32 packing, 0 = int64

// ============ zero degrees + dtype probe (fused; capture-safe) ============
__global__ void zeroprobe_kernel(const void* ei, const void* batch) {
    if (blockIdx.x < 391) {
        int i = blockIdx.x * 256 + threadIdx.x;
        if (i < Nn) g_deg[i] = 0;
    } else {
        int tid = threadIdx.x;
        if (tid == 0) { g_ei32 = 0; g_b32 = 0; }
        __syncthreads();
        const long long* e64 = (const long long*)ei;   // safe range both interps
        long long v = e64[(tid * 997) % Ee];
        if ((unsigned long long)v >= (unsigned long long)Nn) atomicOr(&g_ei32, 1);
        const long long* b64 = (const long long*)batch;
        long long w = b64[(long long)tid * (Nn / 2 - 1) / 255];
        if ((unsigned long long)w >= (unsigned long long)Gg) atomicOr(&g_b32, 1);
    }
}

__device__ __forceinline__ void load_edge(const void* ei, int i, int& src, int& dst) {
    if (i < Ee) {
        if (g_ei32) {
            const int* p = (const int*)ei;
            src = p[i]; dst = p[Ee + i];
        } else {
            const long long* p = (const long long*)ei;
            src = (int)p[i]; dst = (int)p[Ee + i];
        }
    } else {
        src = dst = i - Ee;   // self loops
    }
}

__global__ void count_kernel(const void* ei) {
    int i = blockIdx.x * 256 + threadIdx.x;
    if (i >= ETOT) return;
    int src, dst;
    load_edge(ei, i, src, dst);
    atomicAdd(&g_deg[dst], 1);
}

// ============ 3-phase multi-block exclusive scan ============
__global__ void scanA_kernel() {
    __shared__ int warp_sums[32];
    int tid = threadIdx.x, lane = tid & 31, wid = tid >> 5;
    int i = blockIdx.x * 1024 + tid;
    int v = (i < Nn) ? g_deg[i] : 0;
    int x = v;
#pragma unroll
    for (int off = 1; off < 32; off <<= 1) {
        int y = __shfl_up_sync(0xffffffffu, x, off);
        if (lane >= off) x += y;
    }
    if (lane == 31) warp_sums[wid] = x;
    __syncthreads();
    if (wid == 0) {
        int w = warp_sums[lane];
#pragma unroll
        for (int off = 1; off < 32; off <<= 1) {
            int y = __shfl_up_sync(0xffffffffu, w, off);
            if (lane >= off) w += y;
        }
        warp_sums[lane] = w;
    }
    __syncthreads();
    int woff = wid ? warp_sums[wid - 1] : 0;
    if (i < Nn) g_rowptr[i] = woff + x - v;
    if (tid == 0) g_bsum[blockIdx.x] = warp_sums[31];
}

__global__ void scanB_kernel() {
    __shared__ int ws[4];
    int tid = threadIdx.x, lane = tid & 31, wid = tid >> 5;
    int v = (tid < NB) ? g_bsum[tid] : 0;
    int x = v;
#pragma unroll
    for (int off = 1; off < 32; off <<= 1) {
        int y = __shfl_up_sync(0xffffffffu, x, off);
        if (lane >= off) x += y;
    }
    if (lane == 31) ws[wid] = x;
    __syncthreads();
    int woff = 0;
    for (int k = 0; k < wid; k++) woff += ws[k];
    if (tid < NB) g_boff[tid] = woff + x - v;
    if (tid == 0) g_rowptr[Nn] = ETOT;
}

__global__ void scanC_kernel(const void* batch) {
    int i = blockIdx.x * 1024 + threadIdx.x;
    if (i >= Nn) return;
    int r = g_rowptr[i] + g_boff[blockIdx.x];
    g_rowptr[i] = r;
    g_cursor[i] = r;
    g_batch[i] = g_b32 ? ((const int*)batch)[i] : (int)((const long long*)batch)[i];
}

__global__ void scatter_kernel(const void* ei) {
    int i = blockIdx.x * 256 + threadIdx.x;
    if (i >= ETOT) return;
    int src, dst;
    load_edge(ei, i, src, dst);
    int pos = atomicAdd(&g_cursor[dst], 1);
    g_csrc[pos] = src;
}

// ======== GEMM: h = X @ W (fp16 out), ls/ld reductions. 16 nodes/block ======
template <int F, bool TRANS>
__global__ void gemm_kernel(const float* __restrict__ xin,
                            const float* __restrict__ W,
                            const float* __restrict__ a_s,
                            const float* __restrict__ a_d,
                            const float* __restrict__ bprev) {
    __shared__ float Ws[F * Hh];
    __shared__ float xs[16][F];
    __shared__ float as_s[Hh], ad_s[Hh], bs[Hh];
    __shared__ float ssum[8][4][2];

    int tid = threadIdx.x;                 // 256 threads
    for (int i = tid; i < F * Hh; i += 256) Ws[i] = W[i];
    if (tid < Hh) {
        as_s[tid] = a_s[tid];
        ad_s[tid] = a_d[tid];
        if (TRANS) bs[tid] = bprev[tid];
    }
    __syncthreads();   // bs/Ws visible before staging reads them

    int n0 = blockIdx.x * 16;
    // stage inputs (coalesced over inner dim)
    for (int i = tid; i < 16 * F; i += 256) {
        int node = i / F, col = i % F;
        float v;
        if (TRANS) {
            v = g_agg[(size_t)(n0 + node) * Hh + col] + bs[col];
            v = v > 0.f ? v : (expf(v) - 1.f);   // ELU
        } else {
            v = xin[(n0 + node) * F + col];
        }
        xs[node][col] = v;
    }
    __syncthreads();

    int local = tid >> 6;                  // 0..3 -> node group
    int j     = tid & 63;                  // output column
    float acc[4] = {0.f, 0.f, 0.f, 0.f};
#pragma unroll 16
    for (int k = 0; k < F; k++) {
        float w = Ws[k * Hh + j];
#pragma unroll
        for (int q = 0; q < 4; q++) acc[q] += xs[local * 4 + q][k] * w;
    }
#pragma unroll
    for (int q = 0; q < 4; q++)
        g_hh[(size_t)(n0 + local * 4 + q) * Hh + j] = __float2half(acc[q]);

    float asj = as_s[j], adj = ad_s[j];
    int warp = tid >> 5;
#pragma unroll
    for (int q = 0; q < 4; q++) {
        float rs = acc[q] * asj;
        float rd = acc[q] * adj;
#pragma unroll
        for (int off = 16; off; off >>= 1) {
            rs += __shfl_down_sync(0xffffffffu, rs, off);
            rd += __shfl_down_sync(0xffffffffu, rd, off);
        }
        if ((tid & 31) == 0) { ssum[warp][q][0] = rs; ssum[warp][q][1] = rd; }
    }
    __syncthreads();
    if (j < 4) {   // one thread per (local, q=j)
        int n = n0 + local * 4 + j;
        g_ls[n] = ssum[2 * local][j][0] + ssum[2 * local + 1][j][0];
        g_ld[n] = ssum[2 * local][j][1] + ssum[2 * local + 1][j][1];
    }
}

// ====== aggregation: warp/dst, CSR gather of fp16 h, 2 edges per iter ======
__global__ void agg_kernel() {
    __shared__ float se[8][CAP];
    int gwarp = (blockIdx.x * 256 + threadIdx.x) >> 5;
    int lane  = threadIdx.x & 31;
    int wl    = threadIdx.x >> 5;
    if (gwarp >= Nn) return;
    int dst = gwarp;
    int r0 = g_rowptr[dst], r1 = g_rowptr[dst + 1];
    int d  = r1 - r0;
    float ldv = g_ld[dst];

    // pass 1: logits + max
    float m = -INFINITY;
    for (int k = lane; k < d; k += 32) {
        int src = g_csrc[r0 + k];
        float e = g_ls[src] + ldv;
        e = e > 0.f ? e : 0.2f * e;
        if (k < CAP) se[wl][k] = e;
        m = fmaxf(m, e);
    }
#pragma unroll
    for (int off = 16; off; off >>= 1)
        m = fmaxf(m, __shfl_xor_sync(0xffffffffu, m, off));
    __syncwarp();

    // pass 2: half-warp per edge; each lane loads 4 halves (8B) of h[src]
    int sub = lane >> 4;
    int l16 = lane & 15;
    float4 acc = make_float4(0.f, 0.f, 0.f, 0.f);
    float den = 0.f;
    for (int kk = sub; kk < d; kk += 2) {
        int src = g_csrc[r0 + kk];
        float e;
        if (kk < CAP) e = se[wl][kk];
        else { e = g_ls[src] + ldv; e = e > 0.f ? e : 0.2f * e; }
        float ex = __expf(e - m);
        den += ex;
        const __half2* hp = reinterpret_cast<const __half2*>(g_hh + (size_t)src * Hh + l16 * 4);
        float2 p0 = __half22float2(hp[0]);
        float2 p1 = __half22float2(hp[1]);
        acc.x += ex * p0.x; acc.y += ex * p0.y;
        acc.z += ex * p1.x; acc.w += ex * p1.y;
    }
    den   += __shfl_xor_sync(0xffffffffu, den,   16);
    acc.x += __shfl_xor_sync(0xffffffffu, acc.x, 16);
    acc.y += __shfl_xor_sync(0xffffffffu, acc.y, 16);
    acc.z += __shfl_xor_sync(0xffffffffu, acc.z, 16);
    acc.w += __shfl_xor_sync(0xffffffffu, acc.w, 16);
    if (sub == 0) {
        float inv = 1.f / den;
        float4 o = make_float4(acc.x * inv, acc.y * inv, acc.z * inv, acc.w * inv);
        *reinterpret_cast<float4*>(g_agg + (size_t)dst * Hh + l16 * 4) = o;
    }
}

// ================= pooling: sorted batch -> contiguous ranges ============
__device__ __forceinline__ int lower_bound_batch(int key) {
    int lo = 0, hi = Nn;
    while (lo < hi) {
        int mid = (lo + hi) >> 1;
        if (g_batch[mid] < key) lo = mid + 1; else hi = mid;
    }
    return lo;
}

__global__ void pool_kernel(const float* __restrict__ b4) {
    __shared__ int s_lo, s_hi;
    __shared__ float red[4][Hh];
    int g = blockIdx.x;
    int tid = threadIdx.x;          // 256 threads
    int j = tid & 63, c = tid >> 6;
    if (tid == 0) s_lo = lower_bound_batch(g);
    if (tid == 1) s_hi = lower_bound_batch(g + 1);
    __syncthreads();
    float bj = b4[j];
    float mx = -INFINITY;
    for (int n = s_lo + c; n < s_hi; n += 4) {
        float v = g_agg[(size_t)n * Hh + j] + bj;
        v = v > 0.f ? v : (expf(v) - 1.f);
        mx = fmaxf(mx, v);
    }
    red[c][j] = mx;
    __syncthreads();
    if (c == 0) {
        mx = fmaxf(fmaxf(red[0][j], red[1][j]), fmaxf(red[2][j], red[3][j]));
        g_pool[g * Hh + j] = mx;
    }
}

// ================= final linear =================
__global__ void final_kernel(const float* __restrict__ lw,
                             const float* __restrict__ lb,
                             float* __restrict__ out) {
    int g = blockIdx.x, j = threadIdx.x;   // 64 threads
    float p = g_pool[g * Hh + j];
    if (!isfinite(p)) p = 0.f;
    float c0 = p * lw[j * 2 + 0];
    float c1 = p * lw[j * 2 + 1];
#pragma unroll
    for (int off = 16; off; off >>= 1) {
        c0 += __shfl_down_sync(0xffffffffu, c0, off);
        c1 += __shfl_down_sync(0xffffffffu, c1, off);
    }
    __shared__ float s[2][2];
    if ((j & 31) == 0) { s[j >> 5][0] = c0; s[j >> 5][1] = c1; }
    __syncthreads();
    if (j == 0) {
        out[2 * g + 0] = s[0][0] + s[1][0] + lb[0];
        out[2 * g + 1] = s[0][1] + s[1][1] + lb[1];
    }
}

// ================= launch =================
extern "C" void kernel_launch(void* const* d_in, const int* in_sizes, int n_in,
                              void* d_out, int out_size) {
    const float* x     = (const float*)d_in[0];
    const void*  ei    = d_in[1];
    const void*  batch = d_in[2];
    const float *W[5], *as[5], *ad[5], *b[5];
    for (int l = 0; l < 5; l++) {
        W[l]  = (const float*)d_in[3 + 4 * l];
        as[l] = (const float*)d_in[4 + 4 * l];
        ad[l] = (const float*)d_in[5 + 4 * l];
        b[l]  = (const float*)d_in[6 + 4 * l];
    }
    const float* lw = (const float*)d_in[23];
    const float* lb = (const float*)d_in[24];
    float* out = (float*)d_out;

    zeroprobe_kernel<<<392, 256>>>(ei, batch);
    count_kernel<<<(ETOT + 255) / 256, 256>>>(ei);
    scanA_kernel<<<NB, 1024>>>();
    scanB_kernel<<<1, 128>>>();
    scanC_kernel<<<NB, 1024>>>(batch);
    scatter_kernel<<<(ETOT + 255) / 256, 256>>>(ei);

    for (int l = 0; l < 5; l++) {
        if (l == 0)
            gemm_kernel<14, false><<<Nn / 16, 256>>>(x, W[0], as[0], ad[0], nullptr);
        else
            gemm_kernel<64, true><<<Nn / 16, 256>>>(nullptr, W[l], as[l], ad[l], b[l - 1]);
        agg_kernel<<<(Nn * 32 + 255) / 256, 256>>>();
    }
    pool_kernel<<<Gg, 256>>>(b[4]);
    final_kernel<<<Gg, 64>>>(lw, lb, out);
}